// round 16
// baseline (speedup 1.0000x reference)
#include <cuda_runtime.h>
#include <cuda_fp16.h>
#include <math.h>
#include <stdint.h>

// Problem constants
constexpr int kT = 4096;
constexpr int kC = 2048;
constexpr int kH = 16;
constexpr int kD = 128;
constexpr float kScale = 0.08838834764831845f;

// Scratch (device globals — no cudaMalloc allowed)
__device__ __half g_xh[kT * kC];        // x in fp16
__device__ __half g_wh[4 * kC * kC];    // wq,wk,wv,wo in fp16
__device__ __half g_qh[kT * kC];        // q fp16 (rope'd, scaled)
__device__ __half g_kh[kT * kC];        // k fp16 (rope'd)
__device__ __half g_vh[kT * kC];        // v fp16 [T][C]
__device__ __half g_ch[kT * kC];        // attention output fp16

// ---------------------------------------------------------------------------
__device__ __forceinline__ uint32_t smem_u32(const void* p) {
    uint32_t a;
    asm("{ .reg .u64 t; cvta.to.shared.u64 t, %1; cvt.u32.u64 %0, t; }"
        : "=r"(a) : "l"(p));
    return a;
}

__device__ __forceinline__ void cp_async16(uint32_t saddr, const void* gaddr) {
    asm volatile("cp.async.cg.shared.global [%0], [%1], 16;"
                 :: "r"(saddr), "l"(gaddr));
}
#define CP_COMMIT() asm volatile("cp.async.commit_group;" ::: "memory")

// mma.sync m16n8k16 fp16: D(16x8 f32) += A(16x16 f16) * B(16x8 f16)
__device__ __forceinline__ void mma_f16(float* d, const uint32_t* a,
                                        const uint32_t* b) {
    asm volatile(
        "mma.sync.aligned.m16n8k16.row.col.f32.f16.f16.f32 "
        "{%0,%1,%2,%3}, {%4,%5,%6,%7}, {%8,%9}, {%0,%1,%2,%3};"
        : "+f"(d[0]), "+f"(d[1]), "+f"(d[2]), "+f"(d[3])
        : "r"(a[0]), "r"(a[1]), "r"(a[2]), "r"(a[3]), "r"(b[0]), "r"(b[1]));
}

__device__ __forceinline__ void ldsm_x4(uint32_t& r0, uint32_t& r1,
                                        uint32_t& r2, uint32_t& r3,
                                        uint32_t addr) {
    asm volatile("ldmatrix.sync.aligned.m8n8.x4.shared.b16 {%0,%1,%2,%3}, [%4];"
                 : "=r"(r0), "=r"(r1), "=r"(r2), "=r"(r3) : "r"(addr));
}
__device__ __forceinline__ void ldsm_x4_t(uint32_t& r0, uint32_t& r1,
                                          uint32_t& r2, uint32_t& r3,
                                          uint32_t addr) {
    asm volatile("ldmatrix.sync.aligned.m8n8.x4.trans.shared.b16 {%0,%1,%2,%3}, [%4];"
                 : "=r"(r0), "=r"(r1), "=r"(r2), "=r"(r3) : "r"(addr));
}

// ---------------------------------------------------------------------------
// Fused fp32 -> fp16 conversion: y=0 -> x, y in 1..4 -> weights.
// ---------------------------------------------------------------------------
__global__ void convert_all(const float* __restrict__ x,
                            const float* __restrict__ wq,
                            const float* __restrict__ wk,
                            const float* __restrict__ wv,
                            const float* __restrict__ wo,
                            __half* __restrict__ xh, __half* __restrict__ wh) {
    const int y = blockIdx.y;
    const float* src;
    __half* dst;
    int n4;
    const int CC = kC * kC;
    if (y == 0) { src = x;  dst = xh;           n4 = kT * kC / 4; }
    else if (y == 1) { src = wq; dst = wh;          n4 = CC / 4; }
    else if (y == 2) { src = wk; dst = wh + CC;     n4 = CC / 4; }
    else if (y == 3) { src = wv; dst = wh + 2 * CC; n4 = CC / 4; }
    else             { src = wo; dst = wh + 3 * CC; n4 = CC / 4; }
    int i = blockIdx.x * blockDim.x + threadIdx.x;
    if (i < n4) {
        float4 v = ((const float4*)src)[i];
        __half2 h0 = __floats2half2_rn(v.x, v.y);
        __half2 h1 = __floats2half2_rn(v.z, v.w);
        uint2 u;
        u.x = *(uint32_t*)&h0;
        u.y = *(uint32_t*)&h1;
        *(uint2*)(dst + i * 4) = u;
    }
}

// ---------------------------------------------------------------------------
// FP16 tensor-core GEMM (R15 config — at the legacy-HMMA rate ceiling):
// C[m,n] = sum_k A[m,k]*B[n,k]. CTA tile 128x128x32, 4 warps, warp tile
// 64x64, m16n8k16, 3-stage cp.async, ldmatrix fragments.
// ---------------------------------------------------------------------------
constexpr int GLDH = 40;
constexpr int GSTAGE_HALFS = 2 * 128 * GLDH;
constexpr int GEMM_SMEM_BYTES = 3 * GSTAGE_HALFS * 2;    // 61440

__global__ __launch_bounds__(128, 2) void gemm_h3(
    const __half* __restrict__ A,
    const __half* __restrict__ B0, const __half* __restrict__ B1,
    const __half* __restrict__ B2,
    void* __restrict__ C0, void* __restrict__ C1, void* __restrict__ C2,
    int M, int N, int K, unsigned halfMask) {
    const __half* B = (blockIdx.z == 0) ? B0 : (blockIdx.z == 1) ? B1 : B2;
    void* Cv = (blockIdx.z == 0) ? C0 : (blockIdx.z == 1) ? C1 : C2;
    const bool halfOut = (halfMask >> blockIdx.z) & 1u;

    extern __shared__ __half smh[];
    const uint32_t sb = smem_u32(smh);
    const int tid = threadIdx.x;
    const int lane = tid & 31;
    const int wid = tid >> 5;
    const int warp_m = wid & 1;
    const int warp_n = wid >> 1;
    const int bm = blockIdx.y * 128;
    const int bn = blockIdx.x * 128;

    float d[4][8][4];
#pragma unroll
    for (int mi = 0; mi < 4; mi++)
#pragma unroll
        for (int ni = 0; ni < 8; ni++)
#pragma unroll
            for (int j = 0; j < 4; j++) d[mi][ni][j] = 0.0f;

    const int nStages = K / 32;

    auto prefetch = [&](int s) {
        const int buf = s % 3;
        const uint32_t ab = sb + buf * GSTAGE_HALFS * 2;
        const uint32_t bb = ab + 128 * GLDH * 2;
        const int k0 = s * 32;
#pragma unroll
        for (int j = 0; j < 4; j++) {
            const int idx = tid + j * 128;
            const int row = idx >> 2;
            const int ch = idx & 3;
            const uint32_t soff = (uint32_t)row * 80 + ch * 16;
            cp_async16(ab + soff, &A[(size_t)(bm + row) * K + k0 + ch * 8]);
            cp_async16(bb + soff, &B[(size_t)(bn + row) * K + k0 + ch * 8]);
        }
        CP_COMMIT();
    };

    prefetch(0);
    prefetch(1);

    const int fr = lane >> 2;
    const int fc = lane & 3;
    const int l7 = lane & 7;
    const int lm = lane >> 3;

    const uint32_t aoff = (uint32_t)(warp_m * 64 + (lm & 1) * 8 + l7) * 80
                          + (uint32_t)(lm >> 1) * 16;
    const uint32_t boff = 128u * 80u
                          + (uint32_t)(warp_n * 64 + (lm >> 1) * 8 + l7) * 80
                          + (uint32_t)(lm & 1) * 16;

    for (int s = 0; s < nStages; s++) {
        if (s < nStages - 1) {
            asm volatile("cp.async.wait_group 1;" ::: "memory");
        } else {
            asm volatile("cp.async.wait_group 0;" ::: "memory");
        }
        __syncthreads();
        if (s + 2 < nStages) prefetch(s + 2);

        const uint32_t sbuf = sb + (s % 3) * GSTAGE_HALFS * 2;

#pragma unroll
        for (int kk = 0; kk < 2; kk++) {
            uint32_t a[4][4];
#pragma unroll
            for (int mi = 0; mi < 4; mi++)
                ldsm_x4(a[mi][0], a[mi][1], a[mi][2], a[mi][3],
                        sbuf + aoff + mi * (16 * 80) + kk * 32);
            uint32_t b[8][2];
#pragma unroll
            for (int nj = 0; nj < 4; nj++)
                ldsm_x4(b[2 * nj][0], b[2 * nj][1], b[2 * nj + 1][0],
                        b[2 * nj + 1][1],
                        sbuf + boff + nj * (16 * 80) + kk * 32);
#pragma unroll
            for (int mi = 0; mi < 4; mi++)
#pragma unroll
                for (int ni = 0; ni < 8; ni++)
                    mma_f16(d[mi][ni], a[mi], b[ni]);
        }
    }

    if (halfOut) {
        __half* C = (__half*)Cv;
#pragma unroll
        for (int mi = 0; mi < 4; mi++) {
            const int row = bm + warp_m * 64 + mi * 16 + fr;
#pragma unroll
            for (int ni = 0; ni < 8; ni++) {
                const int col = bn + warp_n * 64 + ni * 8 + fc * 2;
                __half2 h0 = __floats2half2_rn(d[mi][ni][0], d[mi][ni][1]);
                __half2 h1 = __floats2half2_rn(d[mi][ni][2], d[mi][ni][3]);
                *(__half2*)&C[(size_t)row * N + col] = h0;
                *(__half2*)&C[(size_t)(row + 8) * N + col] = h1;
            }
        }
    } else {
        float* C = (float*)Cv;
#pragma unroll
        for (int mi = 0; mi < 4; mi++) {
            const int row = bm + warp_m * 64 + mi * 16 + fr;
#pragma unroll
            for (int ni = 0; ni < 8; ni++) {
                const int col = bn + warp_n * 64 + ni * 8 + fc * 2;
                *(float2*)&C[(size_t)row * N + col] =
                    make_float2(d[mi][ni][0], d[mi][ni][1]);
                *(float2*)&C[(size_t)(row + 8) * N + col] =
                    make_float2(d[mi][ni][2], d[mi][ni][3]);
            }
        }
    }
}

// ---------------------------------------------------------------------------
// RoPE in-place on fp16 Q and K laid out [T, H*D]. Q also scaled by kScale.
// ---------------------------------------------------------------------------
__global__ void rope_kernel(__half* __restrict__ Q, __half* __restrict__ K) {
    const int t = blockIdx.x;
    const float ft = (float)t;
    for (int p = threadIdx.x; p < kH * 64; p += blockDim.x) {
        const int h = p >> 6;
        const int i = p & 63;
        const float inv = __expf(-(float)i * 0.14391157f);
        float s, c;
        sincosf(ft * inv, &s, &c);
        const size_t base = (size_t)t * kC + h * kD;
        {
            float x1 = __half2float(Q[base + i]);
            float x2 = __half2float(Q[base + 64 + i]);
            Q[base + i]      = __float2half_rn((x1 * c - x2 * s) * kScale);
            Q[base + 64 + i] = __float2half_rn((x2 * c + x1 * s) * kScale);
        }
        {
            float x1 = __half2float(K[base + i]);
            float x2 = __half2float(K[base + 64 + i]);
            K[base + i]      = __float2half_rn(x1 * c - x2 * s);
            K[base + 64 + i] = __float2half_rn(x2 * c + x1 * s);
        }
    }
}

// ---------------------------------------------------------------------------
// FA2-style fp16 block-sparse flash attention, 3-CTA/SM variant.
// One CTA per (q-block, head): 64 q rows, 128 threads / 4 warps.
// smem 69.6 KB: persistent Q tile + double-buffered K + single-buffered V
// -> 3 CTAs/SM (12 warps). Q fragments re-loaded per tile via ldmatrix
// (saves 32 regs; launch_bounds(128,3) keeps regs <= 170).
// QK warp tile 16x64, PV 16x128; register softmax; V via ldmatrix.trans.
// allowed(qb,kb) = kb <= qb && (qb-kb <= 16 || kb < 2 || (kb & 3) == 0).
// ---------------------------------------------------------------------------
constexpr int ALDH = 136;    // Q/K/V rows in halfs (272 B)
constexpr int TILE_B = 64 * ALDH * 2;               // 17408 per tile
constexpr int QS_OFF = 0;
constexpr int KS_OFF = QS_OFF + TILE_B;             // x2 bufs
constexpr int VS_OFF = KS_OFF + 2 * TILE_B;         // x1 buf
constexpr int ATTN_SMEM_BYTES = VS_OFF + TILE_B;    // 69632

__global__ __launch_bounds__(128, 3) void attn_h(const __half* __restrict__ Q,
                                                 const __half* __restrict__ K,
                                                 const __half* __restrict__ V,
                                                 __half* __restrict__ Ctx) {
    extern __shared__ char smc[];
    const uint32_t sb = smem_u32(smc);

    const int qb = (gridDim.x - 1) - blockIdx.x;   // heavy-first
    const int h = blockIdx.y;
    const int tid = threadIdx.x;
    const int lane = tid & 31;
    const int wid = tid >> 5;      // 0..3 -> rows wid*16..+15
    const int fr = lane >> 2;
    const int fc = lane & 3;
    const int l7 = lane & 7;
    const int lm = lane >> 3;

    auto is_allowed = [&](int t) {
        return (t <= qb) && (((qb - t) <= 16) || (t < 2) || ((t & 3) == 0));
    };

    auto issueTile = [&](const __half* src, int t, uint32_t base) {
#pragma unroll
        for (int j = 0; j < 8; j++) {
            const int idx = tid + j * 128;
            const int rr = idx >> 4;
            const int ch = idx & 15;
            cp_async16(base + (uint32_t)rr * (ALDH * 2) + ch * 16,
                       &src[(size_t)(t * 64 + rr) * kC + h * kD + ch * 8]);
        }
        CP_COMMIT();
    };

    // Prologue: Q (group 0), K0 (group 1), V0 (group 2)
    issueTile(Q, qb, sb + QS_OFF);
    issueTile(K, 0, sb + KS_OFF);
    issueTile(V, 0, sb + VS_OFF);

    // per-lane ldmatrix offsets
    const uint32_t qfoff = sb + QS_OFF
        + (uint32_t)(wid * 16 + (lm & 1) * 8 + l7) * 272
        + (uint32_t)(lm >> 1) * 16;
    const uint32_t kfoff = (uint32_t)((lm >> 1) * 8 + l7) * 272
                           + (uint32_t)(lm & 1) * 16;
    const uint32_t vfoff = sb + VS_OFF
        + (uint32_t)((lm & 1) * 8 + l7) * 272
        + (uint32_t)(lm >> 1) * 16;

    float m0 = -INFINITY, m1 = -INFINITY, l0 = 0.0f, l1 = 0.0f;
    float o[16][4];
#pragma unroll
    for (int ni = 0; ni < 16; ni++)
#pragma unroll
        for (int j = 0; j < 4; j++) o[ni][j] = 0.0f;

    int kb = 0, ib = 0;

    while (true) {
        int kbn = kb;
        for (int t = kb + 1; t <= qb; t++) {
            if (is_allowed(t)) { kbn = t; break; }
        }

        // wait for K(ib) (Q on first iter too); V(ib) stays pending
        asm volatile("cp.async.wait_group 1;" ::: "memory");
        __syncthreads();

        // ---- S = Q @ K^T : warp tile 16x64, 8 k-steps ----
        const uint32_t kbase = sb + KS_OFF + (ib & 1) * TILE_B;
        float s[8][4];
#pragma unroll
        for (int ni = 0; ni < 8; ni++)
#pragma unroll
            for (int j = 0; j < 4; j++) s[ni][j] = 0.0f;

#pragma unroll
        for (int kk = 0; kk < 8; kk++) {
            uint32_t aq[4];
            ldsm_x4(aq[0], aq[1], aq[2], aq[3], qfoff + kk * 32);
            uint32_t b[8][2];
#pragma unroll
            for (int nj = 0; nj < 4; nj++)
                ldsm_x4(b[2 * nj][0], b[2 * nj][1], b[2 * nj + 1][0],
                        b[2 * nj + 1][1],
                        kbase + kfoff + nj * (16 * 272) + kk * 32);
#pragma unroll
            for (int ni = 0; ni < 8; ni++)
                mma_f16(s[ni], aq, b[ni]);
        }

        // prefetch next K into the other K buffer
        issueTile(K, kbn, sb + KS_OFF + ((ib + 1) & 1) * TILE_B);

        // ---- register softmax (rows wid*16+fr and +8; 16 cols each) ----
        uint32_t pa[4][4];
        {
            float lm0 = -INFINITY, lm1 = -INFINITY;
#pragma unroll
            for (int ni = 0; ni < 8; ni++) {
                lm0 = fmaxf(lm0, fmaxf(s[ni][0], s[ni][1]));
                lm1 = fmaxf(lm1, fmaxf(s[ni][2], s[ni][3]));
            }
            lm0 = fmaxf(lm0, __shfl_xor_sync(0xFFFFFFFFu, lm0, 1));
            lm0 = fmaxf(lm0, __shfl_xor_sync(0xFFFFFFFFu, lm0, 2));
            lm1 = fmaxf(lm1, __shfl_xor_sync(0xFFFFFFFFu, lm1, 1));
            lm1 = fmaxf(lm1, __shfl_xor_sync(0xFFFFFFFFu, lm1, 2));
            const float mn0 = fmaxf(m0, lm0);
            const float mn1 = fmaxf(m1, lm1);
            const float c0r = __expf(m0 - mn0);
            const float c1r = __expf(m1 - mn1);
            float rs0 = 0.0f, rs1 = 0.0f;
#pragma unroll
            for (int ni = 0; ni < 8; ni++) {
                const float e0 = __expf(s[ni][0] - mn0);
                const float e1 = __expf(s[ni][1] - mn0);
                const float e2 = __expf(s[ni][2] - mn1);
                const float e3 = __expf(s[ni][3] - mn1);
                rs0 += e0 + e1;
                rs1 += e2 + e3;
                const __half2 h01 = __floats2half2_rn(e0, e1);
                const __half2 h23 = __floats2half2_rn(e2, e3);
                const int kkk = ni >> 1;
                if ((ni & 1) == 0) {
                    pa[kkk][0] = *(const uint32_t*)&h01;
                    pa[kkk][1] = *(const uint32_t*)&h23;
                } else {
                    pa[kkk][2] = *(const uint32_t*)&h01;
                    pa[kkk][3] = *(const uint32_t*)&h23;
                }
            }
            rs0 += __shfl_xor_sync(0xFFFFFFFFu, rs0, 1);
            rs0 += __shfl_xor_sync(0xFFFFFFFFu, rs0, 2);
            rs1 += __shfl_xor_sync(0xFFFFFFFFu, rs1, 1);
            rs1 += __shfl_xor_sync(0xFFFFFFFFu, rs1, 2);
            l0 = l0 * c0r + rs0;
            l1 = l1 * c1r + rs1;
            m0 = mn0;
            m1 = mn1;
#pragma unroll
            for (int ni = 0; ni < 16; ni++) {
                o[ni][0] *= c0r; o[ni][1] *= c0r;
                o[ni][2] *= c1r; o[ni][3] *= c1r;
            }
        }

        // wait for V(ib); K(ib+1) stays pending
        asm volatile("cp.async.wait_group 1;" ::: "memory");
        __syncthreads();

        // ---- O += P @ V : warp tile 16x128, 4 k-steps (V via trans-ldsm) ----
#pragma unroll
        for (int kk = 0; kk < 4; kk++) {
            uint32_t b[16][2];
#pragma unroll
            for (int nj = 0; nj < 8; nj++)
                ldsm_x4_t(b[2 * nj][0], b[2 * nj][1], b[2 * nj + 1][0],
                          b[2 * nj + 1][1],
                          vfoff + kk * (16 * 272) + nj * 32);
#pragma unroll
            for (int ni = 0; ni < 16; ni++)
                mma_f16(o[ni], pa[kk], b[ni]);
        }

        // single V buffer: all PV reads must finish before the next V lands
        __syncthreads();
        issueTile(V, kbn, sb + VS_OFF);

        if (kbn == kb) break;
        kb = kbn;
        ib++;
    }

    // Drain outstanding prefetches; epilogue is register-only.
    asm volatile("cp.async.wait_group 0;" ::: "memory");

    const float inv0 = 1.0f / l0;
    const float inv1 = 1.0f / l1;
    const int row0 = qb * 64 + wid * 16 + fr;
#pragma unroll
    for (int ni = 0; ni < 16; ni++) {
        const int col = h * kD + ni * 8 + fc * 2;
        __half2 h0 = __floats2half2_rn(o[ni][0] * inv0, o[ni][1] * inv0);
        __half2 h1 = __floats2half2_rn(o[ni][2] * inv1, o[ni][3] * inv1);
        *(__half2*)&Ctx[(size_t)row0 * kC + col] = h0;
        *(__half2*)&Ctx[(size_t)(row0 + 8) * kC + col] = h1;
    }
}

// ---------------------------------------------------------------------------
extern "C" void kernel_launch(void* const* d_in, const int* in_sizes, int n_in,
                              void* d_out, int out_size) {
    const float* x  = (const float*)d_in[0];
    const float* wq = (const float*)d_in[1];
    const float* wk = (const float*)d_in[2];
    const float* wv = (const float*)d_in[3];
    const float* wo = (const float*)d_in[4];
    float* out = (float*)d_out;

    __half *xh, *wh, *qh, *kh, *vh, *ch;
    cudaGetSymbolAddress((void**)&xh, g_xh);
    cudaGetSymbolAddress((void**)&wh, g_wh);
    cudaGetSymbolAddress((void**)&qh, g_qh);
    cudaGetSymbolAddress((void**)&kh, g_kh);
    cudaGetSymbolAddress((void**)&vh, g_vh);
    cudaGetSymbolAddress((void**)&ch, g_ch);

    cudaFuncSetAttribute(gemm_h3, cudaFuncAttributeMaxDynamicSharedMemorySize,
                         GEMM_SMEM_BYTES);
    cudaFuncSetAttribute(attn_h, cudaFuncAttributeMaxDynamicSharedMemorySize,
                         ATTN_SMEM_BYTES);

    const int CC = kC * kC;

    convert_all<<<dim3(kT * kC / 4 / 256, 5), 256>>>(x, wq, wk, wv, wo, xh, wh);

    // Fused QKV projection: q,k,v all fp16 outputs
    gemm_h3<<<dim3(kC / 128, kT / 128, 3), 128, GEMM_SMEM_BYTES>>>(
        xh, wh + 0 * CC, wh + 1 * CC, wh + 2 * CC,
        qh, kh, vh, kT, kC, kC, 7u);

    rope_kernel<<<kT, 256>>>(qh, kh);

    attn_h<<<dim3(kT / 64, kH), 128, ATTN_SMEM_BYTES>>>(qh, kh, vh, ch);

    // Output projection: fp16 in, fp32 out
    gemm_h3<<<dim3(kC / 128, kT / 128, 1), 128, GEMM_SMEM_BYTES>>>(
        ch, wh + 3 * CC, wh + 3 * CC, wh + 3 * CC,
        out, out, out, kT, kC, kC, 0u);
}

// round 17
// speedup vs baseline: 1.0361x; 1.0361x over previous
#include <cuda_runtime.h>
#include <cuda_fp16.h>
#include <math.h>
#include <stdint.h>

// Problem constants
constexpr int kT = 4096;
constexpr int kC = 2048;
constexpr int kH = 16;
constexpr int kD = 128;
constexpr float kScale = 0.08838834764831845f;

// Scratch (device globals — no cudaMalloc allowed)
__device__ __half g_xh[kT * kC];        // x in fp16
__device__ __half g_wh[4 * kC * kC];    // wq,wk,wv,wo in fp16
__device__ __half g_qh[kT * kC];        // q fp16 (rope'd, scaled)
__device__ __half g_kh[kT * kC];        // k fp16 (rope'd)
__device__ __half g_vh[kT * kC];        // v fp16 [T][C]
__device__ __half g_ch[kT * kC];        // attention output fp16

// ---------------------------------------------------------------------------
__device__ __forceinline__ uint32_t smem_u32(const void* p) {
    uint32_t a;
    asm("{ .reg .u64 t; cvta.to.shared.u64 t, %1; cvt.u32.u64 %0, t; }"
        : "=r"(a) : "l"(p));
    return a;
}

__device__ __forceinline__ void cp_async16(uint32_t saddr, const void* gaddr) {
    asm volatile("cp.async.cg.shared.global [%0], [%1], 16;"
                 :: "r"(saddr), "l"(gaddr));
}
#define CP_COMMIT() asm volatile("cp.async.commit_group;" ::: "memory")

// mma.sync m16n8k16 fp16: D(16x8 f32) += A(16x16 f16) * B(16x8 f16)
__device__ __forceinline__ void mma_f16(float* d, const uint32_t* a,
                                        const uint32_t* b) {
    asm volatile(
        "mma.sync.aligned.m16n8k16.row.col.f32.f16.f16.f32 "
        "{%0,%1,%2,%3}, {%4,%5,%6,%7}, {%8,%9}, {%0,%1,%2,%3};"
        : "+f"(d[0]), "+f"(d[1]), "+f"(d[2]), "+f"(d[3])
        : "r"(a[0]), "r"(a[1]), "r"(a[2]), "r"(a[3]), "r"(b[0]), "r"(b[1]));
}

__device__ __forceinline__ void ldsm_x4(uint32_t& r0, uint32_t& r1,
                                        uint32_t& r2, uint32_t& r3,
                                        uint32_t addr) {
    asm volatile("ldmatrix.sync.aligned.m8n8.x4.shared.b16 {%0,%1,%2,%3}, [%4];"
                 : "=r"(r0), "=r"(r1), "=r"(r2), "=r"(r3) : "r"(addr));
}
__device__ __forceinline__ void ldsm_x4_t(uint32_t& r0, uint32_t& r1,
                                          uint32_t& r2, uint32_t& r3,
                                          uint32_t addr) {
    asm volatile("ldmatrix.sync.aligned.m8n8.x4.trans.shared.b16 {%0,%1,%2,%3}, [%4];"
                 : "=r"(r0), "=r"(r1), "=r"(r2), "=r"(r3) : "r"(addr));
}

// ---------------------------------------------------------------------------
// Fused fp32 -> fp16 conversion: y=0 -> x, y in 1..4 -> weights.
// ---------------------------------------------------------------------------
__global__ void convert_all(const float* __restrict__ x,
                            const float* __restrict__ wq,
                            const float* __restrict__ wk,
                            const float* __restrict__ wv,
                            const float* __restrict__ wo,
                            __half* __restrict__ xh, __half* __restrict__ wh) {
    const int y = blockIdx.y;
    const float* src;
    __half* dst;
    int n4;
    const int CC = kC * kC;
    if (y == 0) { src = x;  dst = xh;           n4 = kT * kC / 4; }
    else if (y == 1) { src = wq; dst = wh;          n4 = CC / 4; }
    else if (y == 2) { src = wk; dst = wh + CC;     n4 = CC / 4; }
    else if (y == 3) { src = wv; dst = wh + 2 * CC; n4 = CC / 4; }
    else             { src = wo; dst = wh + 3 * CC; n4 = CC / 4; }
    int i = blockIdx.x * blockDim.x + threadIdx.x;
    if (i < n4) {
        float4 v = ((const float4*)src)[i];
        __half2 h0 = __floats2half2_rn(v.x, v.y);
        __half2 h1 = __floats2half2_rn(v.z, v.w);
        uint2 u;
        u.x = *(uint32_t*)&h0;
        u.y = *(uint32_t*)&h1;
        *(uint2*)(dst + i * 4) = u;
    }
}

// ---------------------------------------------------------------------------
// FP16 tensor-core GEMM: C[m,n] = sum_k A[m,k]*B[n,k], fp32 accumulate.
// CTA tile 128x128x32, 4 warps, warp tile 64x64, m16n8k16, 3-stage cp.async,
// ldmatrix fragments. blockIdx.z selects (B, C).
// halfMask bit z: fp16 output. ropeMask bit z: fuse RoPE into the epilogue
// (N-tile == one 128-dim head; pairs (i, i+64) are tile-local). z==0 also
// applies kScale (query).
// ---------------------------------------------------------------------------
constexpr int GLDH = 40;
constexpr int GSTAGE_HALFS = 2 * 128 * GLDH;
constexpr int GEMM_SMEM_BYTES = 3 * GSTAGE_HALFS * 2;    // 61440

__global__ __launch_bounds__(128, 2) void gemm_h3(
    const __half* __restrict__ A,
    const __half* __restrict__ B0, const __half* __restrict__ B1,
    const __half* __restrict__ B2,
    void* __restrict__ C0, void* __restrict__ C1, void* __restrict__ C2,
    int M, int N, int K, unsigned halfMask, unsigned ropeMask) {
    const __half* B = (blockIdx.z == 0) ? B0 : (blockIdx.z == 1) ? B1 : B2;
    void* Cv = (blockIdx.z == 0) ? C0 : (blockIdx.z == 1) ? C1 : C2;
    const bool halfOut = (halfMask >> blockIdx.z) & 1u;
    const bool doRope = (ropeMask >> blockIdx.z) & 1u;

    extern __shared__ __half smh[];
    const uint32_t sb = smem_u32(smh);
    const int tid = threadIdx.x;
    const int lane = tid & 31;
    const int wid = tid >> 5;
    const int warp_m = wid & 1;
    const int warp_n = wid >> 1;
    const int bm = blockIdx.y * 128;
    const int bn = blockIdx.x * 128;

    float d[4][8][4];
#pragma unroll
    for (int mi = 0; mi < 4; mi++)
#pragma unroll
        for (int ni = 0; ni < 8; ni++)
#pragma unroll
            for (int j = 0; j < 4; j++) d[mi][ni][j] = 0.0f;

    const int nStages = K / 32;

    auto prefetch = [&](int s) {
        const int buf = s % 3;
        const uint32_t ab = sb + buf * GSTAGE_HALFS * 2;
        const uint32_t bb = ab + 128 * GLDH * 2;
        const int k0 = s * 32;
#pragma unroll
        for (int j = 0; j < 4; j++) {
            const int idx = tid + j * 128;
            const int row = idx >> 2;
            const int ch = idx & 3;
            const uint32_t soff = (uint32_t)row * 80 + ch * 16;
            cp_async16(ab + soff, &A[(size_t)(bm + row) * K + k0 + ch * 8]);
            cp_async16(bb + soff, &B[(size_t)(bn + row) * K + k0 + ch * 8]);
        }
        CP_COMMIT();
    };

    prefetch(0);
    prefetch(1);

    const int fr = lane >> 2;
    const int fc = lane & 3;
    const int l7 = lane & 7;
    const int lm = lane >> 3;

    const uint32_t aoff = (uint32_t)(warp_m * 64 + (lm & 1) * 8 + l7) * 80
                          + (uint32_t)(lm >> 1) * 16;
    const uint32_t boff = 128u * 80u
                          + (uint32_t)(warp_n * 64 + (lm >> 1) * 8 + l7) * 80
                          + (uint32_t)(lm & 1) * 16;

    for (int s = 0; s < nStages; s++) {
        if (s < nStages - 1) {
            asm volatile("cp.async.wait_group 1;" ::: "memory");
        } else {
            asm volatile("cp.async.wait_group 0;" ::: "memory");
        }
        __syncthreads();
        if (s + 2 < nStages) prefetch(s + 2);

        const uint32_t sbuf = sb + (s % 3) * GSTAGE_HALFS * 2;

#pragma unroll
        for (int kk = 0; kk < 2; kk++) {
            uint32_t a[4][4];
#pragma unroll
            for (int mi = 0; mi < 4; mi++)
                ldsm_x4(a[mi][0], a[mi][1], a[mi][2], a[mi][3],
                        sbuf + aoff + mi * (16 * 80) + kk * 32);
            uint32_t b[8][2];
#pragma unroll
            for (int nj = 0; nj < 4; nj++)
                ldsm_x4(b[2 * nj][0], b[2 * nj][1], b[2 * nj + 1][0],
                        b[2 * nj + 1][1],
                        sbuf + boff + nj * (16 * 80) + kk * 32);
#pragma unroll
            for (int mi = 0; mi < 4; mi++)
#pragma unroll
                for (int ni = 0; ni < 8; ni++)
                    mma_f16(d[mi][ni], a[mi], b[ni]);
        }
    }

    if (doRope) {
        // Spill accumulators to a fp16 smem tile [128][136], then rope with
        // warp-per-row, coalesced half2 stores. Numerics identical to the
        // old GEMM->fp16->rope->fp16 pipeline.
        __syncthreads();   // stage buffers dead; safe to overwrite
        __half* Dt = smh;
#pragma unroll
        for (int mi = 0; mi < 4; mi++) {
            const int row = warp_m * 64 + mi * 16 + fr;
#pragma unroll
            for (int ni = 0; ni < 8; ni++) {
                const int col = warp_n * 64 + ni * 8 + fc * 2;
                *(__half2*)&Dt[row * 136 + col] =
                    __floats2half2_rn(d[mi][ni][0], d[mi][ni][1]);
                *(__half2*)&Dt[(row + 8) * 136 + col] =
                    __floats2half2_rn(d[mi][ni][2], d[mi][ni][3]);
            }
        }
        __syncthreads();

        __half* C = (__half*)Cv;
        const float scale = (blockIdx.z == 0) ? kScale : 1.0f;
        const int i0 = lane * 2;                 // head-local col 0..62
        const float if0 = __expf(-(float)i0 * 0.14391157f);
        const float if1 = __expf(-(float)(i0 + 1) * 0.14391157f);
        for (int rr = wid; rr < 128; rr += 4) {
            const float ft = (float)(bm + rr);
            float s0, c0, s1, c1;
            sincosf(ft * if0, &s0, &c0);
            sincosf(ft * if1, &s1, &c1);
            const __half2 a = *(const __half2*)&Dt[rr * 136 + i0];
            const __half2 b = *(const __half2*)&Dt[rr * 136 + 64 + i0];
            const float ax = __half2float(a.x), ay = __half2float(a.y);
            const float bx = __half2float(b.x), by = __half2float(b.y);
            const __half2 o1 = __floats2half2_rn((ax * c0 - bx * s0) * scale,
                                                 (ay * c1 - by * s1) * scale);
            const __half2 o2 = __floats2half2_rn((bx * c0 + ax * s0) * scale,
                                                 (by * c1 + ay * s1) * scale);
            *(__half2*)&C[(size_t)(bm + rr) * N + bn + i0] = o1;
            *(__half2*)&C[(size_t)(bm + rr) * N + bn + 64 + i0] = o2;
        }
    } else if (halfOut) {
        __half* C = (__half*)Cv;
#pragma unroll
        for (int mi = 0; mi < 4; mi++) {
            const int row = bm + warp_m * 64 + mi * 16 + fr;
#pragma unroll
            for (int ni = 0; ni < 8; ni++) {
                const int col = bn + warp_n * 64 + ni * 8 + fc * 2;
                __half2 h0 = __floats2half2_rn(d[mi][ni][0], d[mi][ni][1]);
                __half2 h1 = __floats2half2_rn(d[mi][ni][2], d[mi][ni][3]);
                *(__half2*)&C[(size_t)row * N + col] = h0;
                *(__half2*)&C[(size_t)(row + 8) * N + col] = h1;
            }
        }
    } else {
        float* C = (float*)Cv;
#pragma unroll
        for (int mi = 0; mi < 4; mi++) {
            const int row = bm + warp_m * 64 + mi * 16 + fr;
#pragma unroll
            for (int ni = 0; ni < 8; ni++) {
                const int col = bn + warp_n * 64 + ni * 8 + fc * 2;
                *(float2*)&C[(size_t)row * N + col] =
                    make_float2(d[mi][ni][0], d[mi][ni][1]);
                *(float2*)&C[(size_t)(row + 8) * N + col] =
                    make_float2(d[mi][ni][2], d[mi][ni][3]);
            }
        }
    }
}

// ---------------------------------------------------------------------------
// FA2-style fp16 block-sparse flash attention (R15 config — best measured).
// One CTA per (q-block, head): 64 q rows, 128 threads / 4 warps, 2 CTAs/SM.
// QK warp tile 16x64, PV 16x128; register softmax; P repacked in registers.
// V loaded ROW-MAJOR and fragmented via ldmatrix.x4.trans.
// K/V double-buffered; Q fragments hoisted; 2 __syncthreads per tile.
// allowed(qb,kb) = kb <= qb && (qb-kb <= 16 || kb < 2 || (kb & 3) == 0).
// ---------------------------------------------------------------------------
constexpr int ALDH = 136;    // Q/K/V rows in halfs (272 B)
constexpr int TILE_B = 64 * ALDH * 2;               // 17408 per tile
constexpr int QS_OFF = 0;
constexpr int KS_OFF = QS_OFF + TILE_B;             // x2 bufs
constexpr int VS_OFF = KS_OFF + 2 * TILE_B;         // x2 bufs
constexpr int ATTN_SMEM_BYTES = VS_OFF + 2 * TILE_B;  // 87040

__global__ __launch_bounds__(128, 2) void attn_h(const __half* __restrict__ Q,
                                                 const __half* __restrict__ K,
                                                 const __half* __restrict__ V,
                                                 __half* __restrict__ Ctx) {
    extern __shared__ char smc[];
    const uint32_t sb = smem_u32(smc);

    const int qb = (gridDim.x - 1) - blockIdx.x;   // heavy-first
    const int h = blockIdx.y;
    const int tid = threadIdx.x;
    const int lane = tid & 31;
    const int wid = tid >> 5;      // 0..3 -> rows wid*16..+15
    const int fr = lane >> 2;
    const int fc = lane & 3;
    const int l7 = lane & 7;
    const int lm = lane >> 3;

    auto is_allowed = [&](int t) {
        return (t <= qb) && (((qb - t) <= 16) || (t < 2) || ((t & 3) == 0));
    };

    auto issueTile = [&](const __half* src, int t, uint32_t base) {
#pragma unroll
        for (int j = 0; j < 8; j++) {
            const int idx = tid + j * 128;
            const int rr = idx >> 4;
            const int ch = idx & 15;
            cp_async16(base + (uint32_t)rr * (ALDH * 2) + ch * 16,
                       &src[(size_t)(t * 64 + rr) * kC + h * kD + ch * 8]);
        }
        CP_COMMIT();
    };

    // Prologue: Q (group), K0 (group), V0 (group)
    issueTile(Q, qb, sb + QS_OFF);
    issueTile(K, 0, sb + KS_OFF);
    issueTile(V, 0, sb + VS_OFF);

    // Q fragments (tile-invariant): wait for Q only
    asm volatile("cp.async.wait_group 2;" ::: "memory");
    __syncthreads();
    uint32_t aq[8][4];
    {
        const uint32_t qoff = sb + QS_OFF
            + (uint32_t)(wid * 16 + (lm & 1) * 8 + l7) * 272
            + (uint32_t)(lm >> 1) * 16;
#pragma unroll
        for (int kk = 0; kk < 8; kk++)
            ldsm_x4(aq[kk][0], aq[kk][1], aq[kk][2], aq[kk][3],
                    qoff + kk * 32);
    }

    const uint32_t kfoff = (uint32_t)((lm >> 1) * 8 + l7) * 272
                           + (uint32_t)(lm & 1) * 16;
    const uint32_t vfoff = (uint32_t)((lm & 1) * 8 + l7) * 272
                           + (uint32_t)(lm >> 1) * 16;

    float m0 = -INFINITY, m1 = -INFINITY, l0 = 0.0f, l1 = 0.0f;
    float o[16][4];
#pragma unroll
    for (int ni = 0; ni < 16; ni++)
#pragma unroll
        for (int j = 0; j < 4; j++) o[ni][j] = 0.0f;

    int kb = 0, ib = 0;

    while (true) {
        int kbn = kb;
        for (int t = kb + 1; t <= qb; t++) {
            if (is_allowed(t)) { kbn = t; break; }
        }

        // wait for K(ib); V(ib) stays pending
        asm volatile("cp.async.wait_group 1;" ::: "memory");
        __syncthreads();

        // ---- S = Q @ K^T : warp tile 16x64, 8 k-steps ----
        const uint32_t kbase = sb + KS_OFF + (ib & 1) * TILE_B;
        float s[8][4];
#pragma unroll
        for (int ni = 0; ni < 8; ni++)
#pragma unroll
            for (int j = 0; j < 4; j++) s[ni][j] = 0.0f;

#pragma unroll
        for (int kk = 0; kk < 8; kk++) {
            uint32_t b[8][2];
#pragma unroll
            for (int nj = 0; nj < 4; nj++)
                ldsm_x4(b[2 * nj][0], b[2 * nj][1], b[2 * nj + 1][0],
                        b[2 * nj + 1][1],
                        kbase + kfoff + nj * (16 * 272) + kk * 32);
#pragma unroll
            for (int ni = 0; ni < 8; ni++)
                mma_f16(s[ni], aq[kk], b[ni]);
        }

        // prefetch next K into the other buffer
        issueTile(K, kbn, sb + KS_OFF + ((ib + 1) & 1) * TILE_B);

        // ---- register softmax (rows wid*16+fr and +8; 16 cols each) ----
        uint32_t pa[4][4];
        {
            float lm0 = -INFINITY, lm1 = -INFINITY;
#pragma unroll
            for (int ni = 0; ni < 8; ni++) {
                lm0 = fmaxf(lm0, fmaxf(s[ni][0], s[ni][1]));
                lm1 = fmaxf(lm1, fmaxf(s[ni][2], s[ni][3]));
            }
            lm0 = fmaxf(lm0, __shfl_xor_sync(0xFFFFFFFFu, lm0, 1));
            lm0 = fmaxf(lm0, __shfl_xor_sync(0xFFFFFFFFu, lm0, 2));
            lm1 = fmaxf(lm1, __shfl_xor_sync(0xFFFFFFFFu, lm1, 1));
            lm1 = fmaxf(lm1, __shfl_xor_sync(0xFFFFFFFFu, lm1, 2));
            const float mn0 = fmaxf(m0, lm0);
            const float mn1 = fmaxf(m1, lm1);
            const float c0r = __expf(m0 - mn0);
            const float c1r = __expf(m1 - mn1);
            float rs0 = 0.0f, rs1 = 0.0f;
#pragma unroll
            for (int ni = 0; ni < 8; ni++) {
                const float e0 = __expf(s[ni][0] - mn0);
                const float e1 = __expf(s[ni][1] - mn0);
                const float e2 = __expf(s[ni][2] - mn1);
                const float e3 = __expf(s[ni][3] - mn1);
                rs0 += e0 + e1;
                rs1 += e2 + e3;
                const __half2 h01 = __floats2half2_rn(e0, e1);
                const __half2 h23 = __floats2half2_rn(e2, e3);
                const int kkk = ni >> 1;
                if ((ni & 1) == 0) {
                    pa[kkk][0] = *(const uint32_t*)&h01;
                    pa[kkk][1] = *(const uint32_t*)&h23;
                } else {
                    pa[kkk][2] = *(const uint32_t*)&h01;
                    pa[kkk][3] = *(const uint32_t*)&h23;
                }
            }
            rs0 += __shfl_xor_sync(0xFFFFFFFFu, rs0, 1);
            rs0 += __shfl_xor_sync(0xFFFFFFFFu, rs0, 2);
            rs1 += __shfl_xor_sync(0xFFFFFFFFu, rs1, 1);
            rs1 += __shfl_xor_sync(0xFFFFFFFFu, rs1, 2);
            l0 = l0 * c0r + rs0;
            l1 = l1 * c1r + rs1;
            m0 = mn0;
            m1 = mn1;
#pragma unroll
            for (int ni = 0; ni < 16; ni++) {
                o[ni][0] *= c0r; o[ni][1] *= c0r;
                o[ni][2] *= c1r; o[ni][3] *= c1r;
            }
        }

        // wait for V(ib); K(ib+1) stays pending
        asm volatile("cp.async.wait_group 1;" ::: "memory");
        __syncthreads();

        // ---- O += P @ V : warp tile 16x128, 4 k-steps (V via trans-ldsm) ----
        const uint32_t vbase = sb + VS_OFF + (ib & 1) * TILE_B;
#pragma unroll
        for (int kk = 0; kk < 4; kk++) {
            uint32_t b[16][2];
#pragma unroll
            for (int nj = 0; nj < 8; nj++)
                ldsm_x4_t(b[2 * nj][0], b[2 * nj][1], b[2 * nj + 1][0],
                          b[2 * nj + 1][1],
                          vbase + vfoff + kk * (16 * 272) + nj * 32);
#pragma unroll
            for (int ni = 0; ni < 16; ni++)
                mma_f16(o[ni], pa[kk], b[ni]);
        }

        // prefetch next V into the other buffer
        issueTile(V, kbn, sb + VS_OFF + ((ib + 1) & 1) * TILE_B);

        if (kbn == kb) break;
        kb = kbn;
        ib++;
    }

    // Drain outstanding prefetches; epilogue is register-only.
    asm volatile("cp.async.wait_group 0;" ::: "memory");

    const float inv0 = 1.0f / l0;
    const float inv1 = 1.0f / l1;
    const int row0 = qb * 64 + wid * 16 + fr;
#pragma unroll
    for (int ni = 0; ni < 16; ni++) {
        const int col = h * kD + ni * 8 + fc * 2;
        __half2 h0 = __floats2half2_rn(o[ni][0] * inv0, o[ni][1] * inv0);
        __half2 h1 = __floats2half2_rn(o[ni][2] * inv1, o[ni][3] * inv1);
        *(__half2*)&Ctx[(size_t)row0 * kC + col] = h0;
        *(__half2*)&Ctx[(size_t)(row0 + 8) * kC + col] = h1;
    }
}

// ---------------------------------------------------------------------------
extern "C" void kernel_launch(void* const* d_in, const int* in_sizes, int n_in,
                              void* d_out, int out_size) {
    const float* x  = (const float*)d_in[0];
    const float* wq = (const float*)d_in[1];
    const float* wk = (const float*)d_in[2];
    const float* wv = (const float*)d_in[3];
    const float* wo = (const float*)d_in[4];
    float* out = (float*)d_out;

    __half *xh, *wh, *qh, *kh, *vh, *ch;
    cudaGetSymbolAddress((void**)&xh, g_xh);
    cudaGetSymbolAddress((void**)&wh, g_wh);
    cudaGetSymbolAddress((void**)&qh, g_qh);
    cudaGetSymbolAddress((void**)&kh, g_kh);
    cudaGetSymbolAddress((void**)&vh, g_vh);
    cudaGetSymbolAddress((void**)&ch, g_ch);

    cudaFuncSetAttribute(gemm_h3, cudaFuncAttributeMaxDynamicSharedMemorySize,
                         GEMM_SMEM_BYTES);
    cudaFuncSetAttribute(attn_h, cudaFuncAttributeMaxDynamicSharedMemorySize,
                         ATTN_SMEM_BYTES);

    const int CC = kC * kC;

    convert_all<<<dim3(kT * kC / 4 / 256, 5), 256>>>(x, wq, wk, wv, wo, xh, wh);

    // Fused QKV projection: q,k get RoPE fused in the epilogue (ropeMask
    // bits 0,1; q also scaled); v plain fp16 (halfMask bit 2).
    gemm_h3<<<dim3(kC / 128, kT / 128, 3), 128, GEMM_SMEM_BYTES>>>(
        xh, wh + 0 * CC, wh + 1 * CC, wh + 2 * CC,
        qh, kh, vh, kT, kC, kC, 7u, 3u);

    attn_h<<<dim3(kT / 64, kH), 128, ATTN_SMEM_BYTES>>>(qh, kh, vh, ch);

    // Output projection: fp16 in, fp32 out, no rope
    gemm_h3<<<dim3(kC / 128, kT / 128, 1), 128, GEMM_SMEM_BYTES>>>(
        ch, wh + 3 * CC, wh + 3 * CC, wh + 3 * CC,
        out, out, out, kT, kC, kC, 0u, 0u);
}